// round 1
// baseline (speedup 1.0000x reference)
#include <cuda_runtime.h>
#include <cstdint>

#define BATCH   8
#define CH      256
#define HH      80
#define WW      80
#define HW      (HH*WW)          // 6400
#define OC      32               // 2 * groups * scale^2
#define GROUPS  4
#define OH      160
#define OW      160
#define OHW     (OH*OW)          // 25600

// scratch for conv output: 8*32*6400 floats = 6.55 MB
__device__ float g_off[BATCH * OC * HW];

__device__ __forceinline__ unsigned long long pack2(float a, float b) {
    unsigned long long r;
    asm("mov.b64 %0, {%1, %2};" : "=l"(r) : "f"(a), "f"(b));
    return r;
}

__device__ __forceinline__ unsigned long long ffma2(unsigned long long a,
                                                    unsigned long long b,
                                                    unsigned long long c) {
    unsigned long long d;
    asm("fma.rn.f32x2 %0, %1, %2, %3;" : "=l"(d) : "l"(a), "l"(b), "l"(c));
    return d;
}

// ---------------------------------------------------------------------------
// Kernel 1: 1x1 conv  off[b][o][hw] = sum_c x[b][c][hw] * w[o][c] + bias[o]
// Each thread computes 2 adjacent spatial positions (packed f32x2) for all 32
// output channels. 128 threads/block -> 256 positions/block -> 200 blocks.
// ---------------------------------------------------------------------------
__global__ void __launch_bounds__(128)
conv_off_kernel(const float* __restrict__ x,
                const float* __restrict__ wq,
                const float* __restrict__ bias) {
    __shared__ float ws[CH * OC];   // [c][o], 32 KB

    int tid = threadIdx.x;
    for (int idx = tid; idx < CH * OC; idx += 128) {
        int c = idx >> 5;
        int o = idx & 31;
        ws[idx] = wq[o * CH + c];
    }
    __syncthreads();

    int p  = blockIdx.x * 128 + tid;        // pair index, 25600 total
    int b  = p / (HW / 2);
    int pp = p % (HW / 2);

    const float2* xp = reinterpret_cast<const float2*>(x + (size_t)b * CH * HW) + pp;

    unsigned long long acc[OC];
#pragma unroll
    for (int o = 0; o < OC; o++) acc[o] = 0ULL;

#pragma unroll 2
    for (int c = 0; c < CH; c++) {
        float2 xv = __ldg(&xp[c * (HW / 2)]);
        unsigned long long xv2 = pack2(xv.x, xv.y);
        const float* wrow = &ws[c * OC];
#pragma unroll
        for (int o = 0; o < OC; o++) {
            float w = wrow[o];
            acc[o] = ffma2(xv2, pack2(w, w), acc[o]);
        }
    }

    float* offp = g_off + (size_t)b * OC * HW + pp * 2;
#pragma unroll
    for (int o = 0; o < OC; o++) {
        float bo = __ldg(&bias[o]);
        float lo = __uint_as_float((unsigned)(acc[o] & 0xffffffffULL)) + bo;
        float hi = __uint_as_float((unsigned)(acc[o] >> 32)) + bo;
        *reinterpret_cast<float2*>(offp + (size_t)o * HW) = make_float2(lo, hi);
    }
}

// ---------------------------------------------------------------------------
// Kernel 2: bilinear sampling. One thread per (b, gi, oh, ow); loops 64 chans.
//   h = oh/2, i = oh%2, w = ow/2, j = ow%2, k = gi*4 + i*2 + j
//   px = w + 0.25*(off_x + 2j-1),  py = h + 0.25*(off_y + 2i-1)
//   border-clamped bilinear sample of x[b, gi*64 + c] at (px, py)
// ---------------------------------------------------------------------------
__global__ void __launch_bounds__(256)
sample_kernel(const float* __restrict__ x, float* __restrict__ out) {
    int idx = blockIdx.x * 256 + threadIdx.x;   // 819200 threads
    int ow = idx % OW;
    int r  = idx / OW;
    int oh = r % OH;  r /= OH;
    int gi = r & 3;
    int b  = r >> 2;

    int h = oh >> 1, i = oh & 1;
    int w = ow >> 1, j = ow & 1;
    int k = gi * 4 + i * 2 + j;

    const float* offp = g_off + (size_t)b * OC * HW + h * WW + w;
    float offx = offp[(size_t)k * HW];
    float offy = offp[(size_t)(16 + k) * HW];

    float px = (float)w + 0.25f * (offx + (float)(2 * j - 1));
    float py = (float)h + 0.25f * (offy + (float)(2 * i - 1));

    float ix = fminf(fmaxf(px, 0.0f), (float)(WW - 1));
    float iy = fminf(fmaxf(py, 0.0f), (float)(HH - 1));
    float fx = floorf(ix), fy = floorf(iy);
    int x0 = (int)fx, y0 = (int)fy;
    float wx = ix - fx, wy = iy - fy;
    int x1 = min(x0 + 1, WW - 1);
    int y1 = min(y0 + 1, HH - 1);

    float w00 = (1.0f - wy) * (1.0f - wx);
    float w01 = (1.0f - wy) * wx;
    float w10 = wy * (1.0f - wx);
    float w11 = wy * wx;

    int i00 = y0 * WW + x0;
    int i01 = y0 * WW + x1;
    int i10 = y1 * WW + x0;
    int i11 = y1 * WW + x1;

    const float* bp = x + ((size_t)(b * CH + gi * 64)) * HW;
    float* op = out + ((size_t)(b * CH + gi * 64) * OH + oh) * OW + ow;

#pragma unroll 4
    for (int c = 0; c < 64; c++) {
        const float* p = bp + (size_t)c * HW;
        float v;
        v = __ldg(p + i00) * w00;
        v = fmaf(__ldg(p + i01), w01, v);
        v = fmaf(__ldg(p + i10), w10, v);
        v = fmaf(__ldg(p + i11), w11, v);
        op[(size_t)c * OHW] = v;
    }
}

extern "C" void kernel_launch(void* const* d_in, const int* in_sizes, int n_in,
                              void* d_out, int out_size) {
    const float* x    = (const float*)d_in[0];   // [8,256,80,80]
    const float* wq   = (const float*)d_in[1];   // [32,256,1,1]
    const float* bias = (const float*)d_in[2];   // [32]
    float* out = (float*)d_out;                  // [8,256,160,160]

    conv_off_kernel<<<200, 128>>>(x, wq, bias);

    int total = BATCH * GROUPS * OH * OW;        // 819200
    sample_kernel<<<total / 256, 256>>>(x, out);
}